// round 12
// baseline (speedup 1.0000x reference)
#include <cuda_runtime.h>
#include <cuda_fp16.h>
#include <cstdint>

#define N_NODES 100000
#define N_EDGES 1600000
#define D 128
#define CAP 64          // bucket capacity; P(deg>=64) ~ 1e-21 per node

// -------- scratch (device globals; no allocation allowed) --------
__device__ int   g_cnt[N_NODES];
__device__ int   g_bucket[(size_t)N_NODES * CAP];               // 25.6 MB
__device__ __align__(16) __half g_x16[(size_t)N_NODES * D];     // 25.6 MB
__device__ __align__(16) __half g_h1[(size_t)N_NODES * D];      // 25.6 MB
__device__ __align__(16) __half g_wT[4][D * D];                 // W^T fp16, [n][k]

// -------- fused init: zero counters + x->fp16 + W^T fp16 --------
__global__ void k_init(const float* __restrict__ x,
                       const float* __restrict__ W1l, const float* __restrict__ W1r,
                       const float* __restrict__ W2l, const float* __restrict__ W2r,
                       int n, int total4) {
    int i = blockIdx.x * blockDim.x + threadIdx.x;
    if (i < total4) {
        float4 v = *reinterpret_cast<const float4*>(x + (size_t)i * 4);
        __half2 h0 = __floats2half2_rn(v.x, v.y);
        __half2 h1 = __floats2half2_rn(v.z, v.w);
        *reinterpret_cast<uint2*>(g_x16 + (size_t)i * 4) =
            make_uint2(*(uint32_t*)&h0, *(uint32_t*)&h1);
    }
    if (i < n) g_cnt[i] = 0;
    if (i < 65536) {
        int mat = i >> 14;
        int r = (i >> 7) & 127;   // k
        int c = i & 127;          // n
        const float* W = (mat == 0) ? W1l : (mat == 1) ? W1r : (mat == 2) ? W2l : W2r;
        g_wT[mat][c * 128 + r] = __float2half_rn(W[r * 128 + c]);
    }
}

// -------- single-pass bucket fill: 2 edges per thread --------
__global__ void k_fill_bucket(const int* __restrict__ src,
                              const int* __restrict__ dst, int e_cnt) {
    int i = (blockIdx.x * blockDim.x + threadIdx.x) * 2;
    if (i + 1 < e_cnt) {
        int2 s = *reinterpret_cast<const int2*>(src + i);
        int2 d = *reinterpret_cast<const int2*>(dst + i);
        if (d.x >= 0 && d.x < N_NODES) {
            int pos = atomicAdd(&g_cnt[d.x], 1);
            if (pos < CAP) g_bucket[((size_t)d.x << 6) + pos] = s.x;
        }
        if (d.y >= 0 && d.y < N_NODES) {
            int pos = atomicAdd(&g_cnt[d.y], 1);
            if (pos < CAP) g_bucket[((size_t)d.y << 6) + pos] = s.y;
        }
    } else if (i < e_cnt) {
        int s = src[i], d = dst[i];
        if (d >= 0 && d < N_NODES) {
            int pos = atomicAdd(&g_cnt[d], 1);
            if (pos < CAP) g_bucket[((size_t)d << 6) + pos] = s;
        }
    }
}

// ======== fused SAGE layer: gather+mean -> fp16 mma GEMM ========
// CTA: 64 nodes x 128 cols. 8 warps = 2m x 4n, warp tile 32x32.
// smem: mean 64x136h (17408B) + root 2x64x40h (10240B) + B 2x128x40h (20480B)
//     = 48128 B  (<= 48KB static)
#define GT 256
#define MR 64
#define SMS 136   // mean row stride (halfs): 17r mod 8 = r mod 8, conflict-free
#define SP2 40    // streamed row stride (halfs): conflict-free

__device__ __forceinline__ void mma_f16(float c[4], const uint32_t a[4],
                                        const uint32_t b[2]) {
    asm volatile(
        "mma.sync.aligned.m16n8k16.row.col.f32.f16.f16.f32 "
        "{%0,%1,%2,%3}, {%4,%5,%6,%7}, {%8,%9}, {%0,%1,%2,%3};"
        : "+f"(c[0]), "+f"(c[1]), "+f"(c[2]), "+f"(c[3])
        : "r"(a[0]), "r"(a[1]), "r"(a[2]), "r"(a[3]),
          "r"(b[0]), "r"(b[1]));
}

__device__ __forceinline__ void ldsm_x4(uint32_t& r0, uint32_t& r1,
                                        uint32_t& r2, uint32_t& r3, uint32_t addr) {
    asm volatile("ldmatrix.sync.aligned.m8n8.x4.shared.b16 {%0,%1,%2,%3}, [%4];"
                 : "=r"(r0), "=r"(r1), "=r"(r2), "=r"(r3) : "r"(addr));
}

__device__ __forceinline__ uint32_t smem_u32(const void* p) {
    uint32_t a;
    asm("{ .reg .u64 t; cvta.to.shared.u64 t, %1; cvt.u32.u64 %0, t; }"
        : "=r"(a) : "l"(p));
    return a;
}

__device__ __forceinline__ void cp16(uint32_t s_dst, const void* g_src, int src_sz) {
    asm volatile("cp.async.cg.shared.global [%0], [%1], 16, %2;"
                 :: "r"(s_dst), "l"(g_src), "r"(src_sz));
}

__global__ void __launch_bounds__(GT)
k_sage_layer(int layer, const float* __restrict__ bl,
             float* __restrict__ outp, int n) {
    __shared__ __half sMean[MR * SMS];       // 17408 B
    __shared__ __half sRoot[2][MR * SP2];    // 10240 B
    __shared__ __half sB[2][128 * SP2];      // 20480 B

    const __half* feat = layer ? g_h1 : g_x16;     // gather + root source
    const __half* wbase = g_wT[layer * 2];

    int tid = threadIdx.x, lane = tid & 31, warp = tid >> 5;
    int group = lane >> 2, tig = lane & 3;
    int m_base = (warp & 1) * 32;
    int n_base = (warp >> 1) * 32;
    int row0 = blockIdx.x * MR;

    // LDSM lane addressing
    int a_row = m_base + (lane & 15);
    int a_koff = (lane >> 4) * 8;
    int b_row = n_base + ((lane >> 4) << 3) + (lane & 7);
    int b_koff = ((lane >> 3) & 1) * 8;

    auto issue = [&](int cc, int b) {
        int p = cc >> 2;
        int kc = (cc & 3) * 32;
        const __half* wsrc = wbase + p * D * D;
        uint32_t bB = smem_u32(sB[b]);
#pragma unroll
        for (int t = 0; t < 2; t++) {
            int i = tid + t * 256;
            int row = i >> 2;
            int kg8 = (i & 3) * 8;
            cp16(bB + (row * SP2 + kg8) * 2,
                 wsrc + (size_t)row * D + kc + kg8, 16);
        }
        if (cc >= 4) {
            uint32_t rB = smem_u32(sRoot[b]);
            int row = tid >> 2;        // 0..63
            int kg8 = (tid & 3) * 8;
            int node = row0 + row;
            int nodec = node < n ? node : (n - 1);
            cp16(rB + (row * SP2 + kg8) * 2,
                 feat + (size_t)nodec * D + kc + kg8,
                 node < n ? 16 : 0);
        }
        asm volatile("cp.async.commit_group;");
    };

    // prefetch B chunk 0, then gather (copy overlaps gather)
    issue(0, 0);

    // ---- gather + mean: each warp handles 8 nodes ----
#pragma unroll 1
    for (int i = 0; i < 8; i++) {
        int m = warp * 8 + i;
        int node = row0 + m;
        float ax = 0.f, ay = 0.f, az = 0.f, aw = 0.f;
        int cnt = 0;
        if (node < n) {
            const int* bkt = g_bucket + ((size_t)node << 6);
            cnt = min(g_cnt[node], CAP);
            int k = 0;
            for (; k + 2 <= cnt; k += 2) {
                int s0 = __ldg(&bkt[k]);
                int s1 = __ldg(&bkt[k + 1]);
                uint2 p0 = *reinterpret_cast<const uint2*>(feat + (size_t)s0 * D + lane * 4);
                uint2 p1 = *reinterpret_cast<const uint2*>(feat + (size_t)s1 * D + lane * 4);
                float2 a0 = __half22float2(*(const __half2*)&p0.x);
                float2 a1 = __half22float2(*(const __half2*)&p0.y);
                float2 b0 = __half22float2(*(const __half2*)&p1.x);
                float2 b1 = __half22float2(*(const __half2*)&p1.y);
                ax += a0.x + b0.x; ay += a0.y + b0.y;
                az += a1.x + b1.x; aw += a1.y + b1.y;
            }
            if (k < cnt) {
                int s = __ldg(&bkt[k]);
                uint2 p0 = *reinterpret_cast<const uint2*>(feat + (size_t)s * D + lane * 4);
                float2 a0 = __half22float2(*(const __half2*)&p0.x);
                float2 a1 = __half22float2(*(const __half2*)&p0.y);
                ax += a0.x; ay += a0.y; az += a1.x; aw += a1.y;
            }
        }
        float inv = 1.0f / (float)max(cnt, 1);
        __half2 h0 = __floats2half2_rn(ax * inv, ay * inv);
        __half2 h1 = __floats2half2_rn(az * inv, aw * inv);
        *reinterpret_cast<uint2*>(sMean + m * SMS + lane * 4) =
            make_uint2(*(uint32_t*)&h0, *(uint32_t*)&h1);
    }
    __syncthreads();   // mean visible to all warps

    float c[2][4][4];
#pragma unroll
    for (int i = 0; i < 2; i++)
#pragma unroll
        for (int j = 0; j < 4; j++)
#pragma unroll
            for (int q = 0; q < 4; q++) c[i][j][q] = 0.f;

    uint32_t meanU = smem_u32(sMean);

    for (int cc = 0; cc < 8; cc++) {
        int b = cc & 1;
        if (cc < 7) {
            issue(cc + 1, b ^ 1);
            asm volatile("cp.async.wait_group 1;");
        } else {
            asm volatile("cp.async.wait_group 0;");
        }
        __syncthreads();

        // A source: mean (resident, k-offset = chunk) or root stream buffer
        uint32_t aU;
        int aStride, kbase;
        if (cc < 4) { aU = meanU; aStride = SMS; kbase = (cc & 3) * 32; }
        else        { aU = smem_u32(sRoot[b]); aStride = SP2; kbase = 0; }
        uint32_t bU = smem_u32(sB[b]);

#pragma unroll
        for (int ks = 0; ks < 2; ks++) {
            int k0 = ks * 16;
            uint32_t a[2][4], bb[4][2];
#pragma unroll
            for (int i = 0; i < 2; i++)
                ldsm_x4(a[i][0], a[i][1], a[i][2], a[i][3],
                        aU + (uint32_t)(((a_row + i * 16) * aStride) + kbase + k0 + a_koff) * 2);
#pragma unroll
            for (int j2 = 0; j2 < 2; j2++)
                ldsm_x4(bb[2 * j2][0], bb[2 * j2][1], bb[2 * j2 + 1][0], bb[2 * j2 + 1][1],
                        bU + (uint32_t)(((b_row + j2 * 16) * SP2) + k0 + b_koff) * 2);
#pragma unroll
            for (int i = 0; i < 2; i++)
#pragma unroll
                for (int j = 0; j < 4; j++)
                    mma_f16(c[i][j], a[i], bb[j]);
        }
        __syncthreads();
    }

    // ---- epilogue: bias + relu ----
#pragma unroll
    for (int i = 0; i < 2; i++) {
        int r_lo = row0 + m_base + i * 16 + group;
        int r_hi = r_lo + 8;
#pragma unroll
        for (int j = 0; j < 4; j++) {
            int col = n_base + j * 8 + tig * 2;
            float b0 = __ldg(bl + col), b1 = __ldg(bl + col + 1);
            float v00 = fmaxf(c[i][j][0] + b0, 0.f);
            float v01 = fmaxf(c[i][j][1] + b1, 0.f);
            float v10 = fmaxf(c[i][j][2] + b0, 0.f);
            float v11 = fmaxf(c[i][j][3] + b1, 0.f);
            if (layer == 0) {
                if (r_lo < n) {
                    __half2 h = __floats2half2_rn(v00, v01);
                    *reinterpret_cast<__half2*>(g_h1 + (size_t)r_lo * D + col) = h;
                }
                if (r_hi < n) {
                    __half2 h = __floats2half2_rn(v10, v11);
                    *reinterpret_cast<__half2*>(g_h1 + (size_t)r_hi * D + col) = h;
                }
            } else {
                if (r_lo < n)
                    *reinterpret_cast<float2*>(outp + (size_t)r_lo * D + col) =
                        make_float2(v00, v01);
                if (r_hi < n)
                    *reinterpret_cast<float2*>(outp + (size_t)r_hi * D + col) =
                        make_float2(v10, v11);
            }
        }
    }
}

extern "C" void kernel_launch(void* const* d_in, const int* in_sizes, int n_in,
                              void* d_out, int out_size) {
    const float* x   = (const float*)d_in[0];   // [4,25000,128] fp32
    const int*   ei  = (const int*)d_in[1];     // [2, E] int32
    const float* W1l = (const float*)d_in[2];
    const float* b1l = (const float*)d_in[3];
    const float* W1r = (const float*)d_in[4];
    const float* W2l = (const float*)d_in[5];
    const float* b2l = (const float*)d_in[6];
    const float* W2r = (const float*)d_in[7];
    float* out = (float*)d_out;

    int n = in_sizes[0] / D;           // 100000
    int e = in_sizes[1] / 2;           // 1600000
    const int* src = ei;
    const int* dst = ei + e;

    int tb = 256;
    int nb_fill = (e / 2 + tb - 1) / tb;
    int nb_layer = (n + MR - 1) / MR;
    int total4 = n * D / 4;
    int nb_init = (total4 + tb - 1) / tb;

    // ---- fused init + single-pass bucket CSR ----
    k_init<<<nb_init, tb>>>(x, W1l, W1r, W2l, W2r, n, total4);
    k_fill_bucket<<<nb_fill, tb>>>(src, dst, e);

    // ---- layer 1 (fused gather + GEMM): x -> h1 ----
    k_sage_layer<<<nb_layer, GT>>>(/*layer=*/0, b1l, out, n);

    // ---- layer 2 (fused gather + GEMM): h1 -> out ----
    k_sage_layer<<<nb_layer, GT>>>(/*layer=*/1, b2l, out, n);
}

// round 13
// speedup vs baseline: 1.0734x; 1.0734x over previous
#include <cuda_runtime.h>
#include <cuda_fp16.h>
#include <cstdint>

#define N_NODES 100000
#define N_EDGES 1600000
#define D 128
#define CAP 64          // bucket capacity; P(deg>=64) ~ 1e-21 per node

// -------- scratch (device globals; no allocation allowed) --------
__device__ int   g_cnt[N_NODES];
__device__ int   g_bucket[(size_t)N_NODES * CAP];               // 25.6 MB
__device__ __align__(16) __half g_x16[(size_t)N_NODES * D];     // 25.6 MB
__device__ __align__(16) __half g_mean16[(size_t)N_NODES * D];  // 25.6 MB
__device__ __align__(16) __half g_h1[(size_t)N_NODES * D];      // 25.6 MB
__device__ __align__(16) __half g_wT[4][D * D];                 // W^T fp16, [n][k]

// -------- fused init: zero counters + x->fp16 + W^T fp16 --------
__global__ void k_init(const float* __restrict__ x,
                       const float* __restrict__ W1l, const float* __restrict__ W1r,
                       const float* __restrict__ W2l, const float* __restrict__ W2r,
                       int n, int total4) {
    int i = blockIdx.x * blockDim.x + threadIdx.x;
    if (i < total4) {
        float4 v = *reinterpret_cast<const float4*>(x + (size_t)i * 4);
        __half2 h0 = __floats2half2_rn(v.x, v.y);
        __half2 h1 = __floats2half2_rn(v.z, v.w);
        *reinterpret_cast<uint2*>(g_x16 + (size_t)i * 4) =
            make_uint2(*(uint32_t*)&h0, *(uint32_t*)&h1);
    }
    if (i < n) g_cnt[i] = 0;
    if (i < 65536) {
        int mat = i >> 14;
        int r = (i >> 7) & 127;   // k
        int c = i & 127;          // n
        const float* W = (mat == 0) ? W1l : (mat == 1) ? W1r : (mat == 2) ? W2l : W2r;
        g_wT[mat][c * 128 + r] = __float2half_rn(W[r * 128 + c]);
    }
}

// -------- single-pass bucket fill: 2 edges per thread --------
__global__ void k_fill_bucket(const int* __restrict__ src,
                              const int* __restrict__ dst, int e_cnt) {
    int i = (blockIdx.x * blockDim.x + threadIdx.x) * 2;
    if (i + 1 < e_cnt) {
        int2 s = *reinterpret_cast<const int2*>(src + i);
        int2 d = *reinterpret_cast<const int2*>(dst + i);
        if (d.x >= 0 && d.x < N_NODES) {
            int pos = atomicAdd(&g_cnt[d.x], 1);
            if (pos < CAP) g_bucket[((size_t)d.x << 6) + pos] = s.x;
        }
        if (d.y >= 0 && d.y < N_NODES) {
            int pos = atomicAdd(&g_cnt[d.y], 1);
            if (pos < CAP) g_bucket[((size_t)d.y << 6) + pos] = s.y;
        }
    } else if (i < e_cnt) {
        int s = src[i], d = dst[i];
        if (d >= 0 && d < N_NODES) {
            int pos = atomicAdd(&g_cnt[d], 1);
            if (pos < CAP) g_bucket[((size_t)d << 6) + pos] = s;
        }
    }
}

// -------- mean aggregation over fp16 rows: warp/node, fp32 accumulate --------
__global__ void k_aggregate(int use_h1, int n) {
    const __half* feat = use_h1 ? g_h1 : g_x16;
    int warp = (blockIdx.x * blockDim.x + threadIdx.x) >> 5;
    int lane = threadIdx.x & 31;
    if (warp >= n) return;
    const int* bkt = g_bucket + ((size_t)warp << 6);
    int cnt = min(g_cnt[warp], CAP);
    float ax = 0.f, ay = 0.f, az = 0.f, aw = 0.f;
    int k = 0;
    for (; k + 2 <= cnt; k += 2) {
        int s0 = __ldg(&bkt[k]);
        int s1 = __ldg(&bkt[k + 1]);
        uint2 p0 = *reinterpret_cast<const uint2*>(feat + (size_t)s0 * D + lane * 4);
        uint2 p1 = *reinterpret_cast<const uint2*>(feat + (size_t)s1 * D + lane * 4);
        float2 a0 = __half22float2(*(const __half2*)&p0.x);
        float2 a1 = __half22float2(*(const __half2*)&p0.y);
        float2 b0 = __half22float2(*(const __half2*)&p1.x);
        float2 b1 = __half22float2(*(const __half2*)&p1.y);
        ax += a0.x + b0.x; ay += a0.y + b0.y;
        az += a1.x + b1.x; aw += a1.y + b1.y;
    }
    if (k < cnt) {
        int s = __ldg(&bkt[k]);
        uint2 p0 = *reinterpret_cast<const uint2*>(feat + (size_t)s * D + lane * 4);
        float2 a0 = __half22float2(*(const __half2*)&p0.x);
        float2 a1 = __half22float2(*(const __half2*)&p0.y);
        ax += a0.x; ay += a0.y; az += a1.x; aw += a1.y;
    }
    float inv = 1.0f / (float)max(cnt, 1);
    __half2 h0 = __floats2half2_rn(ax * inv, ay * inv);
    __half2 h1 = __floats2half2_rn(az * inv, aw * inv);
    *reinterpret_cast<uint2*>(g_mean16 + (size_t)warp * D + lane * 4) =
        make_uint2(*(uint32_t*)&h0, *(uint32_t*)&h1);
}

// ==== fp16 mma.sync SAGE GEMM, 3-stage cp.async ring + ldmatrix, tile 128x64 ====
#define GT 256
#define SP2 40   // half stride per 32-k row: conflict-free for LDSM

__device__ __forceinline__ void mma_f16(float c[4], const uint32_t a[4],
                                        const uint32_t b[2]) {
    asm volatile(
        "mma.sync.aligned.m16n8k16.row.col.f32.f16.f16.f32 "
        "{%0,%1,%2,%3}, {%4,%5,%6,%7}, {%8,%9}, {%0,%1,%2,%3};"
        : "+f"(c[0]), "+f"(c[1]), "+f"(c[2]), "+f"(c[3])
        : "r"(a[0]), "r"(a[1]), "r"(a[2]), "r"(a[3]),
          "r"(b[0]), "r"(b[1]));
}

__device__ __forceinline__ void ldsm_x4(uint32_t& r0, uint32_t& r1,
                                        uint32_t& r2, uint32_t& r3, uint32_t addr) {
    asm volatile("ldmatrix.sync.aligned.m8n8.x4.shared.b16 {%0,%1,%2,%3}, [%4];"
                 : "=r"(r0), "=r"(r1), "=r"(r2), "=r"(r3) : "r"(addr));
}

__device__ __forceinline__ uint32_t smem_u32(const void* p) {
    uint32_t a;
    asm("{ .reg .u64 t; cvta.to.shared.u64 t, %1; cvt.u32.u64 %0, t; }"
        : "=r"(a) : "l"(p));
    return a;
}

__device__ __forceinline__ void cp16(uint32_t s_dst, const void* g_src, int src_sz) {
    asm volatile("cp.async.cg.shared.global [%0], [%1], 16, %2;"
                 :: "r"(s_dst), "l"(g_src), "r"(src_sz));
}

__global__ void __launch_bounds__(GT)
k_sage_gemm_f16(int root_is_h1, int matBase, const float* __restrict__ bl,
                float* __restrict__ outp, int out_is_h1, int n) {
    __shared__ __half sA[3][128 * SP2];   // 3 x 10 KB
    __shared__ __half sB[3][64 * SP2];    // 3 x 5 KB
    __shared__ float  s_bias[64];

    const __half* rootf = root_is_h1 ? g_h1 : g_x16;

    int tid = threadIdx.x, lane = tid & 31, warp = tid >> 5;
    int group = lane >> 2, tig = lane & 3;
    int m_base = (warp & 3) * 32;
    int n_base = (warp >> 2) * 32;
    int row0 = blockIdx.x * 128;
    int col0 = blockIdx.y * 64;

    if (tid < 64) s_bias[tid] = bl[col0 + tid];

    // LDSM lane addressing
    int a_row = m_base + (lane & 15);
    int a_koff = (lane >> 4) * 8;
    int b_row = n_base + ((lane >> 4) << 3) + (lane & 7);
    int b_koff = ((lane >> 3) & 1) * 8;

    float c[2][4][4];
#pragma unroll
    for (int i = 0; i < 2; i++)
#pragma unroll
        for (int j = 0; j < 4; j++)
#pragma unroll
            for (int q = 0; q < 4; q++) c[i][j][q] = 0.f;

    const __half* wbase = g_wT[matBase];

    auto issue = [&](int cc, int b) {
        int p = cc >> 2;
        int kc = (cc & 3) * 32;
        const __half* asrc = (p == 0) ? g_mean16 : rootf;
        const __half* wsrc = wbase + p * D * D + (size_t)col0 * D;
        uint32_t aB = smem_u32(sA[b]);
        uint32_t bB = smem_u32(sB[b]);
#pragma unroll
        for (int t = 0; t < 2; t++) {
            int i = tid + t * 256;
            int row = i >> 2;
            int kg8 = (i & 3) * 8;
            int node = row0 + row;
            int nodec = node < n ? node : (n - 1);
            cp16(aB + (row * SP2 + kg8) * 2,
                 asrc + (size_t)nodec * D + kc + kg8,
                 node < n ? 16 : 0);
        }
        {
            int row = tid >> 2;          // 0..63
            int kg8 = (tid & 3) * 8;
            cp16(bB + (row * SP2 + kg8) * 2,
                 wsrc + (size_t)row * D + kc + kg8, 16);
        }
        asm volatile("cp.async.commit_group;");
    };

    issue(0, 0);
    issue(1, 1);

    for (int cc = 0; cc < 8; cc++) {
        int b = cc - (cc / 3) * 3;       // cc % 3
        if (cc < 6) {
            issue(cc + 2, (cc + 2) % 3);
            asm volatile("cp.async.wait_group 2;");
        } else if (cc == 6) {
            asm volatile("cp.async.wait_group 1;");
        } else {
            asm volatile("cp.async.wait_group 0;");
        }
        __syncthreads();

        uint32_t cA_u = smem_u32(sA[b]);
        uint32_t cB_u = smem_u32(sB[b]);
#pragma unroll
        for (int ks = 0; ks < 2; ks++) {
            int k0 = ks * 16;
            uint32_t a[2][4], bb[4][2];
#pragma unroll
            for (int i = 0; i < 2; i++)
                ldsm_x4(a[i][0], a[i][1], a[i][2], a[i][3],
                        cA_u + (uint32_t)(((a_row + i * 16) * SP2) + k0 + a_koff) * 2);
#pragma unroll
            for (int j2 = 0; j2 < 2; j2++)
                ldsm_x4(bb[2 * j2][0], bb[2 * j2][1], bb[2 * j2 + 1][0], bb[2 * j2 + 1][1],
                        cB_u + (uint32_t)(((b_row + j2 * 16) * SP2) + k0 + b_koff) * 2);
#pragma unroll
            for (int i = 0; i < 2; i++)
#pragma unroll
                for (int j = 0; j < 4; j++)
                    mma_f16(c[i][j], a[i], bb[j]);
        }
        __syncthreads();   // all warps done with buffer b before refill
    }

    // ---- epilogue: bias + relu ----
#pragma unroll
    for (int i = 0; i < 2; i++) {
        int r_lo = row0 + m_base + i * 16 + group;
        int r_hi = r_lo + 8;
#pragma unroll
        for (int j = 0; j < 4; j++) {
            int col = n_base + j * 8 + tig * 2;
            float b0 = s_bias[col], b1 = s_bias[col + 1];
            int gcol = col0 + col;
            float v00 = fmaxf(c[i][j][0] + b0, 0.f);
            float v01 = fmaxf(c[i][j][1] + b1, 0.f);
            float v10 = fmaxf(c[i][j][2] + b0, 0.f);
            float v11 = fmaxf(c[i][j][3] + b1, 0.f);
            if (out_is_h1) {
                if (r_lo < n) {
                    __half2 h = __floats2half2_rn(v00, v01);
                    *reinterpret_cast<__half2*>(g_h1 + (size_t)r_lo * D + gcol) = h;
                }
                if (r_hi < n) {
                    __half2 h = __floats2half2_rn(v10, v11);
                    *reinterpret_cast<__half2*>(g_h1 + (size_t)r_hi * D + gcol) = h;
                }
            } else {
                if (r_lo < n)
                    *reinterpret_cast<float2*>(outp + (size_t)r_lo * D + gcol) =
                        make_float2(v00, v01);
                if (r_hi < n)
                    *reinterpret_cast<float2*>(outp + (size_t)r_hi * D + gcol) =
                        make_float2(v10, v11);
            }
        }
    }
}

extern "C" void kernel_launch(void* const* d_in, const int* in_sizes, int n_in,
                              void* d_out, int out_size) {
    const float* x   = (const float*)d_in[0];   // [4,25000,128] fp32
    const int*   ei  = (const int*)d_in[1];     // [2, E] int32
    const float* W1l = (const float*)d_in[2];
    const float* b1l = (const float*)d_in[3];
    const float* W1r = (const float*)d_in[4];
    const float* W2l = (const float*)d_in[5];
    const float* b2l = (const float*)d_in[6];
    const float* W2r = (const float*)d_in[7];
    float* out = (float*)d_out;

    int n = in_sizes[0] / D;           // 100000
    int e = in_sizes[1] / 2;           // 1600000
    const int* src = ei;
    const int* dst = ei + e;

    int tb = 256;
    int nb_fill = (e / 2 + tb - 1) / tb;
    int nb_agg = (n + 7) / 8;
    dim3 gemm_grid((n + 127) / 128, 2);
    int total4 = n * D / 4;
    int nb_init = (total4 + tb - 1) / tb;

    // ---- fused init + single-pass bucket CSR ----
    k_init<<<nb_init, tb>>>(x, W1l, W1r, W2l, W2r, n, total4);
    k_fill_bucket<<<nb_fill, tb>>>(src, dst, e);

    // ---- layer 1 ----
    k_aggregate<<<nb_agg, tb>>>(/*use_h1=*/0, n);
    k_sage_gemm_f16<<<gemm_grid, GT>>>(/*root_is_h1=*/0, /*matBase=*/0, b1l,
                                       out, /*out_is_h1=*/1, n);

    // ---- layer 2 ----
    k_aggregate<<<nb_agg, tb>>>(/*use_h1=*/1, n);
    k_sage_gemm_f16<<<gemm_grid, GT>>>(/*root_is_h1=*/1, /*matBase=*/2, b2l,
                                       out, /*out_is_h1=*/0, n);
}

// round 14
// speedup vs baseline: 1.0744x; 1.0010x over previous
#include <cuda_runtime.h>
#include <cuda_fp16.h>
#include <cstdint>

#define N_NODES 100000
#define N_EDGES 1600000
#define D 128
#define CAP 64          // bucket capacity; P(deg>=64) ~ 1e-21 per node

// -------- scratch (device globals; no allocation allowed) --------
__device__ int   g_cnt[N_NODES];
__device__ int   g_bucket[(size_t)N_NODES * CAP];               // 25.6 MB
__device__ __align__(16) __half g_x16[(size_t)N_NODES * D];     // 25.6 MB
__device__ __align__(16) __half g_mean16[(size_t)N_NODES * D];  // 25.6 MB
__device__ __align__(16) __half g_h1[(size_t)N_NODES * D];      // 25.6 MB
__device__ __align__(16) __half g_wT[4][D * D];                 // W^T fp16, [n][k]

// -------- zero counters (main stream, precedes fill) --------
__global__ void k_zero(int n) {
    int i = blockIdx.x * blockDim.x + threadIdx.x;
    if (i < n) g_cnt[i] = 0;
}

// -------- convert x->fp16 + W^T fp16 (side stream, parallel to fill) --------
__global__ void k_convert(const float* __restrict__ x,
                          const float* __restrict__ W1l, const float* __restrict__ W1r,
                          const float* __restrict__ W2l, const float* __restrict__ W2r,
                          int total4) {
    int i = blockIdx.x * blockDim.x + threadIdx.x;
    if (i < total4) {
        float4 v = *reinterpret_cast<const float4*>(x + (size_t)i * 4);
        __half2 h0 = __floats2half2_rn(v.x, v.y);
        __half2 h1 = __floats2half2_rn(v.z, v.w);
        *reinterpret_cast<uint2*>(g_x16 + (size_t)i * 4) =
            make_uint2(*(uint32_t*)&h0, *(uint32_t*)&h1);
    }
    if (i < 65536) {
        int mat = i >> 14;
        int r = (i >> 7) & 127;   // k
        int c = i & 127;          // n
        const float* W = (mat == 0) ? W1l : (mat == 1) ? W1r : (mat == 2) ? W2l : W2r;
        g_wT[mat][c * 128 + r] = __float2half_rn(W[r * 128 + c]);
    }
}

// -------- single-pass bucket fill: 2 edges per thread --------
__global__ void k_fill_bucket(const int* __restrict__ src,
                              const int* __restrict__ dst, int e_cnt) {
    int i = (blockIdx.x * blockDim.x + threadIdx.x) * 2;
    if (i + 1 < e_cnt) {
        int2 s = *reinterpret_cast<const int2*>(src + i);
        int2 d = *reinterpret_cast<const int2*>(dst + i);
        if (d.x >= 0 && d.x < N_NODES) {
            int pos = atomicAdd(&g_cnt[d.x], 1);
            if (pos < CAP) g_bucket[((size_t)d.x << 6) + pos] = s.x;
        }
        if (d.y >= 0 && d.y < N_NODES) {
            int pos = atomicAdd(&g_cnt[d.y], 1);
            if (pos < CAP) g_bucket[((size_t)d.y << 6) + pos] = s.y;
        }
    } else if (i < e_cnt) {
        int s = src[i], d = dst[i];
        if (d >= 0 && d < N_NODES) {
            int pos = atomicAdd(&g_cnt[d], 1);
            if (pos < CAP) g_bucket[((size_t)d << 6) + pos] = s;
        }
    }
}

// -------- mean aggregation over fp16 rows: warp/node, fp32 accumulate --------
__global__ void k_aggregate(int use_h1, int n) {
    const __half* feat = use_h1 ? g_h1 : g_x16;
    int warp = (blockIdx.x * blockDim.x + threadIdx.x) >> 5;
    int lane = threadIdx.x & 31;
    if (warp >= n) return;
    const int* bkt = g_bucket + ((size_t)warp << 6);
    int cnt = min(g_cnt[warp], CAP);
    float ax = 0.f, ay = 0.f, az = 0.f, aw = 0.f;
    int k = 0;
    for (; k + 2 <= cnt; k += 2) {
        int s0 = __ldg(&bkt[k]);
        int s1 = __ldg(&bkt[k + 1]);
        uint2 p0 = *reinterpret_cast<const uint2*>(feat + (size_t)s0 * D + lane * 4);
        uint2 p1 = *reinterpret_cast<const uint2*>(feat + (size_t)s1 * D + lane * 4);
        float2 a0 = __half22float2(*(const __half2*)&p0.x);
        float2 a1 = __half22float2(*(const __half2*)&p0.y);
        float2 b0 = __half22float2(*(const __half2*)&p1.x);
        float2 b1 = __half22float2(*(const __half2*)&p1.y);
        ax += a0.x + b0.x; ay += a0.y + b0.y;
        az += a1.x + b1.x; aw += a1.y + b1.y;
    }
    if (k < cnt) {
        int s = __ldg(&bkt[k]);
        uint2 p0 = *reinterpret_cast<const uint2*>(feat + (size_t)s * D + lane * 4);
        float2 a0 = __half22float2(*(const __half2*)&p0.x);
        float2 a1 = __half22float2(*(const __half2*)&p0.y);
        ax += a0.x; ay += a0.y; az += a1.x; aw += a1.y;
    }
    float inv = 1.0f / (float)max(cnt, 1);
    __half2 h0 = __floats2half2_rn(ax * inv, ay * inv);
    __half2 h1 = __floats2half2_rn(az * inv, aw * inv);
    *reinterpret_cast<uint2*>(g_mean16 + (size_t)warp * D + lane * 4) =
        make_uint2(*(uint32_t*)&h0, *(uint32_t*)&h1);
}

// ==== fp16 mma.sync SAGE GEMM, 3-stage ring, single barrier/chunk ====
#define GT 256
#define SP2 40   // half stride per 32-k row: conflict-free for LDSM

__device__ __forceinline__ void mma_f16(float c[4], const uint32_t a[4],
                                        const uint32_t b[2]) {
    asm volatile(
        "mma.sync.aligned.m16n8k16.row.col.f32.f16.f16.f32 "
        "{%0,%1,%2,%3}, {%4,%5,%6,%7}, {%8,%9}, {%0,%1,%2,%3};"
        : "+f"(c[0]), "+f"(c[1]), "+f"(c[2]), "+f"(c[3])
        : "r"(a[0]), "r"(a[1]), "r"(a[2]), "r"(a[3]),
          "r"(b[0]), "r"(b[1]));
}

__device__ __forceinline__ void ldsm_x4(uint32_t& r0, uint32_t& r1,
                                        uint32_t& r2, uint32_t& r3, uint32_t addr) {
    asm volatile("ldmatrix.sync.aligned.m8n8.x4.shared.b16 {%0,%1,%2,%3}, [%4];"
                 : "=r"(r0), "=r"(r1), "=r"(r2), "=r"(r3) : "r"(addr));
}

__device__ __forceinline__ uint32_t smem_u32(const void* p) {
    uint32_t a;
    asm("{ .reg .u64 t; cvta.to.shared.u64 t, %1; cvt.u32.u64 %0, t; }"
        : "=r"(a) : "l"(p));
    return a;
}

__device__ __forceinline__ void cp16(uint32_t s_dst, const void* g_src, int src_sz) {
    asm volatile("cp.async.cg.shared.global [%0], [%1], 16, %2;"
                 :: "r"(s_dst), "l"(g_src), "r"(src_sz));
}

__global__ void __launch_bounds__(GT)
k_sage_gemm_f16(int root_is_h1, int matBase, const float* __restrict__ bl,
                float* __restrict__ outp, int out_is_h1, int n) {
    __shared__ __half sA[3][128 * SP2];   // 3 x 10 KB
    __shared__ __half sB[3][64 * SP2];    // 3 x 5 KB
    __shared__ float  s_bias[64];

    const __half* rootf = root_is_h1 ? g_h1 : g_x16;

    int tid = threadIdx.x, lane = tid & 31, warp = tid >> 5;
    int group = lane >> 2, tig = lane & 3;
    int m_base = (warp & 3) * 32;
    int n_base = (warp >> 2) * 32;
    int row0 = blockIdx.x * 128;
    int col0 = blockIdx.y * 64;

    if (tid < 64) s_bias[tid] = bl[col0 + tid];

    // LDSM lane addressing
    int a_row = m_base + (lane & 15);
    int a_koff = (lane >> 4) * 8;
    int b_row = n_base + ((lane >> 4) << 3) + (lane & 7);
    int b_koff = ((lane >> 3) & 1) * 8;

    float c[2][4][4];
#pragma unroll
    for (int i = 0; i < 2; i++)
#pragma unroll
        for (int j = 0; j < 4; j++)
#pragma unroll
            for (int q = 0; q < 4; q++) c[i][j][q] = 0.f;

    const __half* wbase = g_wT[matBase];

    auto issue = [&](int cc, int b) {
        int p = cc >> 2;
        int kc = (cc & 3) * 32;
        const __half* asrc = (p == 0) ? g_mean16 : rootf;
        const __half* wsrc = wbase + p * D * D + (size_t)col0 * D;
        uint32_t aB = smem_u32(sA[b]);
        uint32_t bB = smem_u32(sB[b]);
#pragma unroll
        for (int t = 0; t < 2; t++) {
            int i = tid + t * 256;
            int row = i >> 2;
            int kg8 = (i & 3) * 8;
            int node = row0 + row;
            int nodec = node < n ? node : (n - 1);
            cp16(aB + (row * SP2 + kg8) * 2,
                 asrc + (size_t)nodec * D + kc + kg8,
                 node < n ? 16 : 0);
        }
        {
            int row = tid >> 2;          // 0..63
            int kg8 = (tid & 3) * 8;
            cp16(bB + (row * SP2 + kg8) * 2,
                 wsrc + (size_t)row * D + kc + kg8, 16);
        }
        asm volatile("cp.async.commit_group;");
    };

    issue(0, 0);
    issue(1, 1);

    for (int cc = 0; cc < 8; cc++) {
        int b = cc - (cc / 3) * 3;       // cc % 3
        if (cc < 7) asm volatile("cp.async.wait_group 1;");
        else        asm volatile("cp.async.wait_group 0;");
        __syncthreads();                 // chunk cc ready; all warps done with (cc-1)%3
        if (cc < 6) issue(cc + 2, (cc + 2) % 3);

        uint32_t cA_u = smem_u32(sA[b]);
        uint32_t cB_u = smem_u32(sB[b]);
#pragma unroll
        for (int ks = 0; ks < 2; ks++) {
            int k0 = ks * 16;
            uint32_t a[2][4], bb[4][2];
#pragma unroll
            for (int i = 0; i < 2; i++)
                ldsm_x4(a[i][0], a[i][1], a[i][2], a[i][3],
                        cA_u + (uint32_t)(((a_row + i * 16) * SP2) + k0 + a_koff) * 2);
#pragma unroll
            for (int j2 = 0; j2 < 2; j2++)
                ldsm_x4(bb[2 * j2][0], bb[2 * j2][1], bb[2 * j2 + 1][0], bb[2 * j2 + 1][1],
                        cB_u + (uint32_t)(((b_row + j2 * 16) * SP2) + k0 + b_koff) * 2);
#pragma unroll
            for (int i = 0; i < 2; i++)
#pragma unroll
                for (int j = 0; j < 4; j++)
                    mma_f16(c[i][j], a[i], bb[j]);
        }
    }

    // ---- epilogue: bias + relu ----
#pragma unroll
    for (int i = 0; i < 2; i++) {
        int r_lo = row0 + m_base + i * 16 + group;
        int r_hi = r_lo + 8;
#pragma unroll
        for (int j = 0; j < 4; j++) {
            int col = n_base + j * 8 + tig * 2;
            float b0 = s_bias[col], b1 = s_bias[col + 1];
            int gcol = col0 + col;
            float v00 = fmaxf(c[i][j][0] + b0, 0.f);
            float v01 = fmaxf(c[i][j][1] + b1, 0.f);
            float v10 = fmaxf(c[i][j][2] + b0, 0.f);
            float v11 = fmaxf(c[i][j][3] + b1, 0.f);
            if (out_is_h1) {
                if (r_lo < n) {
                    __half2 h = __floats2half2_rn(v00, v01);
                    *reinterpret_cast<__half2*>(g_h1 + (size_t)r_lo * D + gcol) = h;
                }
                if (r_hi < n) {
                    __half2 h = __floats2half2_rn(v10, v11);
                    *reinterpret_cast<__half2*>(g_h1 + (size_t)r_hi * D + gcol) = h;
                }
            } else {
                if (r_lo < n)
                    *reinterpret_cast<float2*>(outp + (size_t)r_lo * D + gcol) =
                        make_float2(v00, v01);
                if (r_hi < n)
                    *reinterpret_cast<float2*>(outp + (size_t)r_hi * D + gcol) =
                        make_float2(v10, v11);
            }
        }
    }
}

extern "C" void kernel_launch(void* const* d_in, const int* in_sizes, int n_in,
                              void* d_out, int out_size) {
    const float* x   = (const float*)d_in[0];   // [4,25000,128] fp32
    const int*   ei  = (const int*)d_in[1];     // [2, E] int32
    const float* W1l = (const float*)d_in[2];
    const float* b1l = (const float*)d_in[3];
    const float* W1r = (const float*)d_in[4];
    const float* W2l = (const float*)d_in[5];
    const float* b2l = (const float*)d_in[6];
    const float* W2r = (const float*)d_in[7];
    float* out = (float*)d_out;

    int n = in_sizes[0] / D;           // 100000
    int e = in_sizes[1] / 2;           // 1600000
    const int* src = ei;
    const int* dst = ei + e;

    // one-time side stream + fork/join events (host resources only)
    static cudaStream_t s2 = nullptr;
    static cudaEvent_t evFork = nullptr, evJoin = nullptr;
    if (s2 == nullptr) {
        cudaStreamCreateWithFlags(&s2, cudaStreamNonBlocking);
        cudaEventCreateWithFlags(&evFork, cudaEventDisableTiming);
        cudaEventCreateWithFlags(&evJoin, cudaEventDisableTiming);
    }

    int tb = 256;
    int nb_zero = (n + tb - 1) / tb;
    int nb_fill = (e / 2 + tb - 1) / tb;
    int nb_agg = (n + 7) / 8;
    dim3 gemm_grid((n + 127) / 128, 2);
    int total4 = n * D / 4;
    int nb_cv = (total4 + tb - 1) / tb;

    // ---- fork: convert (s2) runs parallel to zero+fill (main) ----
    cudaEventRecord(evFork, 0);
    cudaStreamWaitEvent(s2, evFork, 0);
    k_convert<<<nb_cv, tb, 0, s2>>>(x, W1l, W1r, W2l, W2r, total4);
    k_zero<<<nb_zero, tb>>>(n);
    k_fill_bucket<<<nb_fill, tb>>>(src, dst, e);
    cudaEventRecord(evJoin, s2);
    cudaStreamWaitEvent(0, evJoin, 0);

    // ---- layer 1 ----
    k_aggregate<<<nb_agg, tb>>>(/*use_h1=*/0, n);
    k_sage_gemm_f16<<<gemm_grid, GT>>>(/*root_is_h1=*/0, /*matBase=*/0, b1l,
                                       out, /*out_is_h1=*/1, n);

    // ---- layer 2 ----
    k_aggregate<<<nb_agg, tb>>>(/*use_h1=*/1, n);
    k_sage_gemm_f16<<<gemm_grid, GT>>>(/*root_is_h1=*/1, /*matBase=*/2, b2l,
                                       out, /*out_is_h1=*/0, n);
}

// round 15
// speedup vs baseline: 1.1663x; 1.0855x over previous
#include <cuda_runtime.h>
#include <cuda_fp16.h>
#include <cstdint>

#define N_NODES 100000
#define N_EDGES 1600000
#define D 128
#define CAP 64          // bucket capacity; P(deg>=64) ~ 1e-21 per node

// -------- scratch (device globals; no allocation allowed) --------
__device__ int   g_cnt[N_NODES];
__device__ int   g_bucket[(size_t)N_NODES * CAP];               // 25.6 MB
__device__ __align__(16) __half g_x16[(size_t)N_NODES * D];     // 25.6 MB
__device__ __align__(16) __half g_mean16[(size_t)N_NODES * D];  // 25.6 MB
__device__ __align__(16) __half g_h1[(size_t)N_NODES * D];      // 25.6 MB
__device__ __align__(16) __half g_wT[4][D * D];                 // W^T fp16, [n][k]

// -------- fused init: zero counters + x->fp16 + W^T fp16 --------
__global__ void k_init(const float* __restrict__ x,
                       const float* __restrict__ W1l, const float* __restrict__ W1r,
                       const float* __restrict__ W2l, const float* __restrict__ W2r,
                       int n, int total4) {
    int i = blockIdx.x * blockDim.x + threadIdx.x;
    if (i < total4) {
        float4 v = *reinterpret_cast<const float4*>(x + (size_t)i * 4);
        __half2 h0 = __floats2half2_rn(v.x, v.y);
        __half2 h1 = __floats2half2_rn(v.z, v.w);
        *reinterpret_cast<uint2*>(g_x16 + (size_t)i * 4) =
            make_uint2(*(uint32_t*)&h0, *(uint32_t*)&h1);
    }
    if (i < n) g_cnt[i] = 0;
    if (i < 65536) {
        int mat = i >> 14;
        int r = (i >> 7) & 127;   // k
        int c = i & 127;          // n
        const float* W = (mat == 0) ? W1l : (mat == 1) ? W1r : (mat == 2) ? W2l : W2r;
        g_wT[mat][c * 128 + r] = __float2half_rn(W[r * 128 + c]);
    }
}

// -------- single-pass bucket fill: 2 edges per thread --------
__global__ void k_fill_bucket(const int* __restrict__ src,
                              const int* __restrict__ dst, int e_cnt) {
    int i = (blockIdx.x * blockDim.x + threadIdx.x) * 2;
    if (i + 1 < e_cnt) {
        int2 s = *reinterpret_cast<const int2*>(src + i);
        int2 d = *reinterpret_cast<const int2*>(dst + i);
        if (d.x >= 0 && d.x < N_NODES) {
            int pos = atomicAdd(&g_cnt[d.x], 1);
            if (pos < CAP) g_bucket[((size_t)d.x << 6) + pos] = s.x;
        }
        if (d.y >= 0 && d.y < N_NODES) {
            int pos = atomicAdd(&g_cnt[d.y], 1);
            if (pos < CAP) g_bucket[((size_t)d.y << 6) + pos] = s.y;
        }
    } else if (i < e_cnt) {
        int s = src[i], d = dst[i];
        if (d >= 0 && d < N_NODES) {
            int pos = atomicAdd(&g_cnt[d], 1);
            if (pos < CAP) g_bucket[((size_t)d << 6) + pos] = s;
        }
    }
}

// ---- mean aggregation: fp16 pairwise pre-add, fp32 accumulate ----
__global__ void k_aggregate(int use_h1, int n) {
    const __half* feat = use_h1 ? g_h1 : g_x16;
    int warp = (blockIdx.x * blockDim.x + threadIdx.x) >> 5;
    int lane = threadIdx.x & 31;
    if (warp >= n) return;
    const int* bkt = g_bucket + ((size_t)warp << 6);
    int cnt = min(g_cnt[warp], CAP);
    float ax = 0.f, ay = 0.f, az = 0.f, aw = 0.f;
    int k = 0;
    // 4 neighbors per iteration: two independent fp16 pair chains
    for (; k + 4 <= cnt; k += 4) {
        int s0 = __ldg(&bkt[k]);
        int s1 = __ldg(&bkt[k + 1]);
        int s2 = __ldg(&bkt[k + 2]);
        int s3 = __ldg(&bkt[k + 3]);
        uint2 p0 = *reinterpret_cast<const uint2*>(feat + (size_t)s0 * D + lane * 4);
        uint2 p1 = *reinterpret_cast<const uint2*>(feat + (size_t)s1 * D + lane * 4);
        uint2 p2 = *reinterpret_cast<const uint2*>(feat + (size_t)s2 * D + lane * 4);
        uint2 p3 = *reinterpret_cast<const uint2*>(feat + (size_t)s3 * D + lane * 4);
        __half2 q0 = __hadd2(*(const __half2*)&p0.x, *(const __half2*)&p1.x);
        __half2 q1 = __hadd2(*(const __half2*)&p0.y, *(const __half2*)&p1.y);
        __half2 r0 = __hadd2(*(const __half2*)&p2.x, *(const __half2*)&p3.x);
        __half2 r1 = __hadd2(*(const __half2*)&p2.y, *(const __half2*)&p3.y);
        float2 f0 = __half22float2(q0);
        float2 f1 = __half22float2(q1);
        float2 g0 = __half22float2(r0);
        float2 g1 = __half22float2(r1);
        ax += f0.x + g0.x; ay += f0.y + g0.y;
        az += f1.x + g1.x; aw += f1.y + g1.y;
    }
    if (k + 2 <= cnt) {
        int s0 = __ldg(&bkt[k]);
        int s1 = __ldg(&bkt[k + 1]);
        uint2 p0 = *reinterpret_cast<const uint2*>(feat + (size_t)s0 * D + lane * 4);
        uint2 p1 = *reinterpret_cast<const uint2*>(feat + (size_t)s1 * D + lane * 4);
        __half2 q0 = __hadd2(*(const __half2*)&p0.x, *(const __half2*)&p1.x);
        __half2 q1 = __hadd2(*(const __half2*)&p0.y, *(const __half2*)&p1.y);
        float2 f0 = __half22float2(q0);
        float2 f1 = __half22float2(q1);
        ax += f0.x; ay += f0.y; az += f1.x; aw += f1.y;
        k += 2;
    }
    if (k < cnt) {
        int s = __ldg(&bkt[k]);
        uint2 p0 = *reinterpret_cast<const uint2*>(feat + (size_t)s * D + lane * 4);
        float2 a0 = __half22float2(*(const __half2*)&p0.x);
        float2 a1 = __half22float2(*(const __half2*)&p0.y);
        ax += a0.x; ay += a0.y; az += a1.x; aw += a1.y;
    }
    float inv = 1.0f / (float)max(cnt, 1);
    __half2 h0 = __floats2half2_rn(ax * inv, ay * inv);
    __half2 h1 = __floats2half2_rn(az * inv, aw * inv);
    *reinterpret_cast<uint2*>(g_mean16 + (size_t)warp * D + lane * 4) =
        make_uint2(*(uint32_t*)&h0, *(uint32_t*)&h1);
}

// ======== fp16 mma.sync SAGE GEMM, cp.async + ldmatrix, tile 128x128 ========
#define GT 256
#define SP2 40   // half stride per 32-k row: conflict-free for LDS/LDSM

__device__ __forceinline__ void mma_f16(float c[4], const uint32_t a[4],
                                        const uint32_t b[2]) {
    asm volatile(
        "mma.sync.aligned.m16n8k16.row.col.f32.f16.f16.f32 "
        "{%0,%1,%2,%3}, {%4,%5,%6,%7}, {%8,%9}, {%0,%1,%2,%3};"
        : "+f"(c[0]), "+f"(c[1]), "+f"(c[2]), "+f"(c[3])
        : "r"(a[0]), "r"(a[1]), "r"(a[2]), "r"(a[3]),
          "r"(b[0]), "r"(b[1]));
}

__device__ __forceinline__ void ldsm_x4(uint32_t& r0, uint32_t& r1,
                                        uint32_t& r2, uint32_t& r3, uint32_t addr) {
    asm volatile("ldmatrix.sync.aligned.m8n8.x4.shared.b16 {%0,%1,%2,%3}, [%4];"
                 : "=r"(r0), "=r"(r1), "=r"(r2), "=r"(r3) : "r"(addr));
}

__device__ __forceinline__ uint32_t smem_u32(const void* p) {
    uint32_t a;
    asm("{ .reg .u64 t; cvta.to.shared.u64 t, %1; cvt.u32.u64 %0, t; }"
        : "=r"(a) : "l"(p));
    return a;
}

__device__ __forceinline__ void cp16(uint32_t s_dst, const void* g_src, int src_sz) {
    asm volatile("cp.async.cg.shared.global [%0], [%1], 16, %2;"
                 :: "r"(s_dst), "l"(g_src), "r"(src_sz));
}

__global__ void __launch_bounds__(GT)
k_sage_gemm_f16(int root_is_h1, int matBase, const float* __restrict__ bl,
                float* __restrict__ outp, int out_is_h1, int n) {
    __shared__ __half sA[2][128 * SP2];   // 2 x 10 KB
    __shared__ __half sB[2][128 * SP2];   // 2 x 10 KB
    __shared__ float  s_bias[128];

    const __half* rootf = root_is_h1 ? g_h1 : g_x16;

    int tid = threadIdx.x, lane = tid & 31, warp = tid >> 5;
    int group = lane >> 2, tig = lane & 3;
    int m_base = (warp & 3) * 32;
    int n_base = (warp >> 2) * 64;
    int row0 = blockIdx.x * 128;

    if (tid < 128) s_bias[tid] = bl[tid];

    // LDSM lane addressing
    int a_row = m_base + (lane & 15);
    int a_koff = (lane >> 4) * 8;
    int b_row = n_base + ((lane >> 4) << 3) + (lane & 7);
    int b_koff = ((lane >> 3) & 1) * 8;

    float c[2][8][4];
#pragma unroll
    for (int i = 0; i < 2; i++)
#pragma unroll
        for (int j = 0; j < 8; j++)
#pragma unroll
            for (int q = 0; q < 4; q++) c[i][j][q] = 0.f;

    const __half* wbase = g_wT[matBase];

    auto issue = [&](int cc, int b) {
        int p = cc >> 2;
        int kc = (cc & 3) * 32;
        const __half* asrc = (p == 0) ? g_mean16 : rootf;
        const __half* wsrc = wbase + p * D * D;
        uint32_t aB = smem_u32(sA[b]);
        uint32_t bB = smem_u32(sB[b]);
#pragma unroll
        for (int t = 0; t < 2; t++) {
            int i = tid + t * 256;
            int row = i >> 2;
            int kg8 = (i & 3) * 8;
            int node = row0 + row;
            int nodec = node < n ? node : (n - 1);
            cp16(aB + (row * SP2 + kg8) * 2,
                 asrc + (size_t)nodec * D + kc + kg8,
                 node < n ? 16 : 0);
            cp16(bB + (row * SP2 + kg8) * 2,
                 wsrc + (size_t)row * D + kc + kg8, 16);
        }
        asm volatile("cp.async.commit_group;");
    };

    issue(0, 0);

    for (int cc = 0; cc < 8; cc++) {
        int b = cc & 1;
        if (cc < 7) {
            issue(cc + 1, b ^ 1);
            asm volatile("cp.async.wait_group 1;");
        } else {
            asm volatile("cp.async.wait_group 0;");
        }
        __syncthreads();

        uint32_t cA_u = smem_u32(sA[b]);
        uint32_t cB_u = smem_u32(sB[b]);
#pragma unroll
        for (int ks = 0; ks < 2; ks++) {
            int k0 = ks * 16;
            uint32_t a[2][4], bb[8][2];
#pragma unroll
            for (int i = 0; i < 2; i++)
                ldsm_x4(a[i][0], a[i][1], a[i][2], a[i][3],
                        cA_u + (uint32_t)(((a_row + i * 16) * SP2) + k0 + a_koff) * 2);
#pragma unroll
            for (int j2 = 0; j2 < 4; j2++)
                ldsm_x4(bb[2 * j2][0], bb[2 * j2][1], bb[2 * j2 + 1][0], bb[2 * j2 + 1][1],
                        cB_u + (uint32_t)(((b_row + j2 * 16) * SP2) + k0 + b_koff) * 2);
#pragma unroll
            for (int i = 0; i < 2; i++)
#pragma unroll
                for (int j = 0; j < 8; j++)
                    mma_f16(c[i][j], a[i], bb[j]);
        }
        __syncthreads();
    }

    // ---- epilogue: bias + relu ----
#pragma unroll
    for (int i = 0; i < 2; i++) {
        int r_lo = row0 + m_base + i * 16 + group;
        int r_hi = r_lo + 8;
#pragma unroll
        for (int j = 0; j < 8; j++) {
            int col = n_base + j * 8 + tig * 2;
            float b0 = s_bias[col], b1 = s_bias[col + 1];
            float v00 = fmaxf(c[i][j][0] + b0, 0.f);
            float v01 = fmaxf(c[i][j][1] + b1, 0.f);
            float v10 = fmaxf(c[i][j][2] + b0, 0.f);
            float v11 = fmaxf(c[i][j][3] + b1, 0.f);
            if (out_is_h1) {
                if (r_lo < n) {
                    __half2 h = __floats2half2_rn(v00, v01);
                    *reinterpret_cast<__half2*>(g_h1 + (size_t)r_lo * D + col) = h;
                }
                if (r_hi < n) {
                    __half2 h = __floats2half2_rn(v10, v11);
                    *reinterpret_cast<__half2*>(g_h1 + (size_t)r_hi * D + col) = h;
                }
            } else {
                if (r_lo < n)
                    *reinterpret_cast<float2*>(outp + (size_t)r_lo * D + col) =
                        make_float2(v00, v01);
                if (r_hi < n)
                    *reinterpret_cast<float2*>(outp + (size_t)r_hi * D + col) =
                        make_float2(v10, v11);
            }
        }
    }
}

extern "C" void kernel_launch(void* const* d_in, const int* in_sizes, int n_in,
                              void* d_out, int out_size) {
    const float* x   = (const float*)d_in[0];   // [4,25000,128] fp32
    const int*   ei  = (const int*)d_in[1];     // [2, E] int32
    const float* W1l = (const float*)d_in[2];
    const float* b1l = (const float*)d_in[3];
    const float* W1r = (const float*)d_in[4];
    const float* W2l = (const float*)d_in[5];
    const float* b2l = (const float*)d_in[6];
    const float* W2r = (const float*)d_in[7];
    float* out = (float*)d_out;

    int n = in_sizes[0] / D;           // 100000
    int e = in_sizes[1] / 2;           // 1600000
    const int* src = ei;
    const int* dst = ei + e;

    int tb = 256;
    int nb_fill = (e / 2 + tb - 1) / tb;
    int nb_agg = (n + 7) / 8;
    int nb_gemm = (n + 127) / 128;
    int total4 = n * D / 4;
    int nb_init = (total4 + tb - 1) / tb;

    // ---- fused init + single-pass bucket CSR ----
    k_init<<<nb_init, tb>>>(x, W1l, W1r, W2l, W2r, n, total4);
    k_fill_bucket<<<nb_fill, tb>>>(src, dst, e);

    // ---- layer 1 ----
    k_aggregate<<<nb_agg, tb>>>(/*use_h1=*/0, n);
    k_sage_gemm_f16<<<nb_gemm, GT>>>(/*root_is_h1=*/0, /*matBase=*/0, b1l,
                                     out, /*out_is_h1=*/1, n);

    // ---- layer 2 ----
    k_aggregate<<<nb_agg, tb>>>(/*use_h1=*/1, n);
    k_sage_gemm_f16<<<nb_gemm, GT>>>(/*root_is_h1=*/1, /*matBase=*/2, b2l,
                                     out, /*out_is_h1=*/0, n);
}

// round 16
// speedup vs baseline: 1.1722x; 1.0051x over previous
#include <cuda_runtime.h>
#include <cuda_fp16.h>
#include <cstdint>

#define N_NODES 100000
#define N_EDGES 1600000
#define D 128
#define CAP 64          // bucket capacity; P(deg>=64) ~ 1e-21 per node

// -------- scratch (device globals; no allocation allowed) --------
__device__ int   g_cnt[N_NODES];
__device__ int   g_bucket[(size_t)N_NODES * CAP];               // 25.6 MB
__device__ __align__(16) __half g_x16[(size_t)N_NODES * D];     // 25.6 MB
__device__ __align__(16) __half g_mean16[(size_t)N_NODES * D];  // 25.6 MB
__device__ __align__(16) __half g_h1[(size_t)N_NODES * D];      // 25.6 MB
__device__ __align__(16) __half g_wT[4][D * D];                 // W^T fp16, [n][k]

// -------- fused init: zero counters + x->fp16 + W^T fp16 --------
__global__ void k_init(const float* __restrict__ x,
                       const float* __restrict__ W1l, const float* __restrict__ W1r,
                       const float* __restrict__ W2l, const float* __restrict__ W2r,
                       int n, int total4) {
    int i = blockIdx.x * blockDim.x + threadIdx.x;
    if (i < total4) {
        float4 v = *reinterpret_cast<const float4*>(x + (size_t)i * 4);
        __half2 h0 = __floats2half2_rn(v.x, v.y);
        __half2 h1 = __floats2half2_rn(v.z, v.w);
        *reinterpret_cast<uint2*>(g_x16 + (size_t)i * 4) =
            make_uint2(*(uint32_t*)&h0, *(uint32_t*)&h1);
    }
    if (i < n) g_cnt[i] = 0;
    if (i < 65536) {
        int mat = i >> 14;
        int r = (i >> 7) & 127;   // k
        int c = i & 127;          // n
        const float* W = (mat == 0) ? W1l : (mat == 1) ? W1r : (mat == 2) ? W2l : W2r;
        g_wT[mat][c * 128 + r] = __float2half_rn(W[r * 128 + c]);
    }
}

// -------- single-pass bucket fill: 2 edges per thread --------
__global__ void k_fill_bucket(const int* __restrict__ src,
                              const int* __restrict__ dst, int e_cnt) {
    int i = (blockIdx.x * blockDim.x + threadIdx.x) * 2;
    if (i + 1 < e_cnt) {
        int2 s = *reinterpret_cast<const int2*>(src + i);
        int2 d = *reinterpret_cast<const int2*>(dst + i);
        if (d.x >= 0 && d.x < N_NODES) {
            int pos = atomicAdd(&g_cnt[d.x], 1);
            if (pos < CAP) g_bucket[((size_t)d.x << 6) + pos] = s.x;
        }
        if (d.y >= 0 && d.y < N_NODES) {
            int pos = atomicAdd(&g_cnt[d.y], 1);
            if (pos < CAP) g_bucket[((size_t)d.y << 6) + pos] = s.y;
        }
    } else if (i < e_cnt) {
        int s = src[i], d = dst[i];
        if (d >= 0 && d < N_NODES) {
            int pos = atomicAdd(&g_cnt[d], 1);
            if (pos < CAP) g_bucket[((size_t)d << 6) + pos] = s;
        }
    }
}

// ---- mean aggregation: 2 nodes/warp, uint4 lanes, fp16 pair pre-add ----
__global__ void k_aggregate(int use_h1, int n) {
    const __half* feat = use_h1 ? g_h1 : g_x16;
    int gw = (blockIdx.x * blockDim.x + threadIdx.x) >> 5;   // warp id
    int lane = threadIdx.x & 31;
    int half = lane >> 4;          // 0 -> node A, 1 -> node B
    int hl = lane & 15;            // lane within half: 8 halfs each
    int node = gw * 2 + half;
    if (node >= n) return;
    const int* bkt = g_bucket + ((size_t)node << 6);
    int cnt = min(g_cnt[node], CAP);

    float a0 = 0.f, a1 = 0.f, a2 = 0.f, a3 = 0.f;
    float a4 = 0.f, a5 = 0.f, a6 = 0.f, a7 = 0.f;
    int k = 0;
    for (; k + 2 <= cnt; k += 2) {
        int s0 = __ldg(&bkt[k]);
        int s1 = __ldg(&bkt[k + 1]);
        uint4 p0 = *reinterpret_cast<const uint4*>(feat + (size_t)s0 * D + hl * 8);
        uint4 p1 = *reinterpret_cast<const uint4*>(feat + (size_t)s1 * D + hl * 8);
        __half2 q0 = __hadd2(*(const __half2*)&p0.x, *(const __half2*)&p1.x);
        __half2 q1 = __hadd2(*(const __half2*)&p0.y, *(const __half2*)&p1.y);
        __half2 q2 = __hadd2(*(const __half2*)&p0.z, *(const __half2*)&p1.z);
        __half2 q3 = __hadd2(*(const __half2*)&p0.w, *(const __half2*)&p1.w);
        float2 f0 = __half22float2(q0);
        float2 f1 = __half22float2(q1);
        float2 f2 = __half22float2(q2);
        float2 f3 = __half22float2(q3);
        a0 += f0.x; a1 += f0.y; a2 += f1.x; a3 += f1.y;
        a4 += f2.x; a5 += f2.y; a6 += f3.x; a7 += f3.y;
    }
    if (k < cnt) {
        int s = __ldg(&bkt[k]);
        uint4 p0 = *reinterpret_cast<const uint4*>(feat + (size_t)s * D + hl * 8);
        float2 f0 = __half22float2(*(const __half2*)&p0.x);
        float2 f1 = __half22float2(*(const __half2*)&p0.y);
        float2 f2 = __half22float2(*(const __half2*)&p0.z);
        float2 f3 = __half22float2(*(const __half2*)&p0.w);
        a0 += f0.x; a1 += f0.y; a2 += f1.x; a3 += f1.y;
        a4 += f2.x; a5 += f2.y; a6 += f3.x; a7 += f3.y;
    }
    float inv = 1.0f / (float)max(cnt, 1);
    __half2 h0 = __floats2half2_rn(a0 * inv, a1 * inv);
    __half2 h1 = __floats2half2_rn(a2 * inv, a3 * inv);
    __half2 h2 = __floats2half2_rn(a4 * inv, a5 * inv);
    __half2 h3 = __floats2half2_rn(a6 * inv, a7 * inv);
    uint4 pk;
    pk.x = *(uint32_t*)&h0; pk.y = *(uint32_t*)&h1;
    pk.z = *(uint32_t*)&h2; pk.w = *(uint32_t*)&h3;
    *reinterpret_cast<uint4*>(g_mean16 + (size_t)node * D + hl * 8) = pk;
}

// ======== fp16 mma.sync SAGE GEMM, cp.async + ldmatrix, tile 128x128 ========
#define GT 256
#define SP2 40   // half stride per 32-k row: conflict-free for LDS/LDSM

__device__ __forceinline__ void mma_f16(float c[4], const uint32_t a[4],
                                        const uint32_t b[2]) {
    asm volatile(
        "mma.sync.aligned.m16n8k16.row.col.f32.f16.f16.f32 "
        "{%0,%1,%2,%3}, {%4,%5,%6,%7}, {%8,%9}, {%0,%1,%2,%3};"
        : "+f"(c[0]), "+f"(c[1]), "+f"(c[2]), "+f"(c[3])
        : "r"(a[0]), "r"(a[1]), "r"(a[2]), "r"(a[3]),
          "r"(b[0]), "r"(b[1]));
}

__device__ __forceinline__ void ldsm_x4(uint32_t& r0, uint32_t& r1,
                                        uint32_t& r2, uint32_t& r3, uint32_t addr) {
    asm volatile("ldmatrix.sync.aligned.m8n8.x4.shared.b16 {%0,%1,%2,%3}, [%4];"
                 : "=r"(r0), "=r"(r1), "=r"(r2), "=r"(r3) : "r"(addr));
}

__device__ __forceinline__ uint32_t smem_u32(const void* p) {
    uint32_t a;
    asm("{ .reg .u64 t; cvta.to.shared.u64 t, %1; cvt.u32.u64 %0, t; }"
        : "=r"(a) : "l"(p));
    return a;
}

__device__ __forceinline__ void cp16(uint32_t s_dst, const void* g_src, int src_sz) {
    asm volatile("cp.async.cg.shared.global [%0], [%1], 16, %2;"
                 :: "r"(s_dst), "l"(g_src), "r"(src_sz));
}

__global__ void __launch_bounds__(GT)
k_sage_gemm_f16(int root_is_h1, int matBase, const float* __restrict__ bl,
                float* __restrict__ outp, int out_is_h1, int n) {
    __shared__ __half sA[2][128 * SP2];   // 2 x 10 KB
    __shared__ __half sB[2][128 * SP2];   // 2 x 10 KB
    __shared__ float  s_bias[128];

    const __half* rootf = root_is_h1 ? g_h1 : g_x16;

    int tid = threadIdx.x, lane = tid & 31, warp = tid >> 5;
    int group = lane >> 2, tig = lane & 3;
    int m_base = (warp & 3) * 32;
    int n_base = (warp >> 2) * 64;
    int row0 = blockIdx.x * 128;

    if (tid < 128) s_bias[tid] = bl[tid];

    // LDSM lane addressing
    int a_row = m_base + (lane & 15);
    int a_koff = (lane >> 4) * 8;
    int b_row = n_base + ((lane >> 4) << 3) + (lane & 7);
    int b_koff = ((lane >> 3) & 1) * 8;

    float c[2][8][4];
#pragma unroll
    for (int i = 0; i < 2; i++)
#pragma unroll
        for (int j = 0; j < 8; j++)
#pragma unroll
            for (int q = 0; q < 4; q++) c[i][j][q] = 0.f;

    const __half* wbase = g_wT[matBase];

    auto issue = [&](int cc, int b) {
        int p = cc >> 2;
        int kc = (cc & 3) * 32;
        const __half* asrc = (p == 0) ? g_mean16 : rootf;
        const __half* wsrc = wbase + p * D * D;
        uint32_t aB = smem_u32(sA[b]);
        uint32_t bB = smem_u32(sB[b]);
#pragma unroll
        for (int t = 0; t < 2; t++) {
            int i = tid + t * 256;
            int row = i >> 2;
            int kg8 = (i & 3) * 8;
            int node = row0 + row;
            int nodec = node < n ? node : (n - 1);
            cp16(aB + (row * SP2 + kg8) * 2,
                 asrc + (size_t)nodec * D + kc + kg8,
                 node < n ? 16 : 0);
            cp16(bB + (row * SP2 + kg8) * 2,
                 wsrc + (size_t)row * D + kc + kg8, 16);
        }
        asm volatile("cp.async.commit_group;");
    };

    issue(0, 0);

    for (int cc = 0; cc < 8; cc++) {
        int b = cc & 1;
        if (cc < 7) {
            issue(cc + 1, b ^ 1);
            asm volatile("cp.async.wait_group 1;");
        } else {
            asm volatile("cp.async.wait_group 0;");
        }
        __syncthreads();

        uint32_t cA_u = smem_u32(sA[b]);
        uint32_t cB_u = smem_u32(sB[b]);
#pragma unroll
        for (int ks = 0; ks < 2; ks++) {
            int k0 = ks * 16;
            uint32_t a[2][4], bb[8][2];
#pragma unroll
            for (int i = 0; i < 2; i++)
                ldsm_x4(a[i][0], a[i][1], a[i][2], a[i][3],
                        cA_u + (uint32_t)(((a_row + i * 16) * SP2) + k0 + a_koff) * 2);
#pragma unroll
            for (int j2 = 0; j2 < 4; j2++)
                ldsm_x4(bb[2 * j2][0], bb[2 * j2][1], bb[2 * j2 + 1][0], bb[2 * j2 + 1][1],
                        cB_u + (uint32_t)(((b_row + j2 * 16) * SP2) + k0 + b_koff) * 2);
#pragma unroll
            for (int i = 0; i < 2; i++)
#pragma unroll
                for (int j = 0; j < 8; j++)
                    mma_f16(c[i][j], a[i], bb[j]);
        }
        __syncthreads();
    }

    // ---- epilogue: bias + relu ----
#pragma unroll
    for (int i = 0; i < 2; i++) {
        int r_lo = row0 + m_base + i * 16 + group;
        int r_hi = r_lo + 8;
#pragma unroll
        for (int j = 0; j < 8; j++) {
            int col = n_base + j * 8 + tig * 2;
            float b0 = s_bias[col], b1 = s_bias[col + 1];
            float v00 = fmaxf(c[i][j][0] + b0, 0.f);
            float v01 = fmaxf(c[i][j][1] + b1, 0.f);
            float v10 = fmaxf(c[i][j][2] + b0, 0.f);
            float v11 = fmaxf(c[i][j][3] + b1, 0.f);
            if (out_is_h1) {
                if (r_lo < n) {
                    __half2 h = __floats2half2_rn(v00, v01);
                    *reinterpret_cast<__half2*>(g_h1 + (size_t)r_lo * D + col) = h;
                }
                if (r_hi < n) {
                    __half2 h = __floats2half2_rn(v10, v11);
                    *reinterpret_cast<__half2*>(g_h1 + (size_t)r_hi * D + col) = h;
                }
            } else {
                if (r_lo < n)
                    *reinterpret_cast<float2*>(outp + (size_t)r_lo * D + col) =
                        make_float2(v00, v01);
                if (r_hi < n)
                    *reinterpret_cast<float2*>(outp + (size_t)r_hi * D + col) =
                        make_float2(v10, v11);
            }
        }
    }
}

extern "C" void kernel_launch(void* const* d_in, const int* in_sizes, int n_in,
                              void* d_out, int out_size) {
    const float* x   = (const float*)d_in[0];   // [4,25000,128] fp32
    const int*   ei  = (const int*)d_in[1];     // [2, E] int32
    const float* W1l = (const float*)d_in[2];
    const float* b1l = (const float*)d_in[3];
    const float* W1r = (const float*)d_in[4];
    const float* W2l = (const float*)d_in[5];
    const float* b2l = (const float*)d_in[6];
    const float* W2r = (const float*)d_in[7];
    float* out = (float*)d_out;

    int n = in_sizes[0] / D;           // 100000
    int e = in_sizes[1] / 2;           // 1600000
    const int* src = ei;
    const int* dst = ei + e;

    int tb = 256;
    int nb_fill = (e / 2 + tb - 1) / tb;
    int nb_agg = ((n + 1) / 2 + 7) / 8;     // 2 nodes per warp, 8 warps per block
    int nb_gemm = (n + 127) / 128;
    int total4 = n * D / 4;
    int nb_init = (total4 + tb - 1) / tb;

    // ---- fused init + single-pass bucket CSR ----
    k_init<<<nb_init, tb>>>(x, W1l, W1r, W2l, W2r, n, total4);
    k_fill_bucket<<<nb_fill, tb>>>(src, dst, e);

    // ---- layer 1 ----
    k_aggregate<<<nb_agg, tb>>>(/*use_h1=*/0, n);
    k_sage_gemm_f16<<<nb_gemm, GT>>>(/*root_is_h1=*/0, /*matBase=*/0, b1l,
                                     out, /*out_is_h1=*/1, n);

    // ---- layer 2 ----
    k_aggregate<<<nb_agg, tb>>>(/*use_h1=*/1, n);
    k_sage_gemm_f16<<<nb_gemm, GT>>>(/*root_is_h1=*/1, /*matBase=*/2, b2l,
                                     out, /*out_is_h1=*/0, n);
}